// round 16
// baseline (speedup 1.0000x reference)
#include <cuda_runtime.h>
#include <cuda_bf16.h>
#include <cooperative_groups.h>

namespace cg = cooperative_groups;

// Problem constants
#define Bb   2
#define Nn   16384
#define Ss   4096
#define Kk   32
#define Fin  16
#define FD   19      // Fin + 3
#define H1D  64
#define H2D  64
#define H3D  128

// -------- scratch (device globals; no allocation allowed) --------
__device__ float g_centers[Bb * Ss * 3];
__device__ int   g_nbr[Bb * Ss * Kk];
__device__ int   g_cnt[Bb * Ss];

typedef unsigned long long u64;

__device__ __forceinline__ u64 pk2(float lo, float hi) {
    u64 r; asm("mov.b64 %0, {%1, %2};" : "=l"(r) : "f"(lo), "f"(hi)); return r;
}
__device__ __forceinline__ void upk2(u64 v, float& lo, float& hi) {
    asm("mov.b64 {%0, %1}, %2;" : "=f"(lo), "=f"(hi) : "l"(v));
}
__device__ __forceinline__ u64 add2(u64 a, u64 b) {
    u64 r; asm("add.rn.f32x2 %0, %1, %2;" : "=l"(r) : "l"(a), "l"(b)); return r;
}
__device__ __forceinline__ u64 mul2(u64 a, u64 b) {
    u64 r; asm("mul.rn.f32x2 %0, %1, %2;" : "=l"(r) : "l"(a), "l"(b)); return r;
}
__device__ __forceinline__ u64 fma2(u64 a, u64 b, u64 c) {
    u64 r; asm("fma.rn.f32x2 %0, %1, %2, %3;" : "=l"(r) : "l"(a), "l"(b), "l"(c)); return r;
}
__device__ __forceinline__ unsigned smem_u32(const void* p) {
    unsigned a;
    asm("{ .reg .u64 t; cvta.to.shared.u64 t, %1; cvt.u32.u64 %0, t; }" : "=r"(a) : "l"(p));
    return a;
}
__device__ __forceinline__ unsigned mapa_u32(unsigned addr, unsigned rank) {
    unsigned r; asm("mapa.shared::cluster.u32 %0, %1, %2;" : "=r"(r) : "r"(addr), "r"(rank));
    return r;
}
__device__ __forceinline__ void st_rem_u64(unsigned addr, u64 v) {
    asm volatile("st.shared::cluster.u64 [%0], %1;" :: "r"(addr), "l"(v) : "memory");
}
__device__ __forceinline__ void mbar_init(unsigned addr, unsigned cnt) {
    asm volatile("mbarrier.init.shared.b64 [%0], %1;" :: "r"(addr), "r"(cnt) : "memory");
}
__device__ __forceinline__ void mbar_arrive_rel_cluster(unsigned addr) {
    asm volatile("mbarrier.arrive.release.cluster.shared::cluster.b64 _, [%0];"
                 :: "r"(addr) : "memory");
}
__device__ __forceinline__ void mbar_wait_acq_cluster(unsigned addr, unsigned parity) {
    asm volatile(
        "{\n\t.reg .pred P;\n"
        "W_%=:\n\t"
        "mbarrier.try_wait.parity.acquire.cluster.shared::cta.b64 P, [%0], %1, 0x989680;\n\t"
        "@!P bra W_%=;\n\t}"
        :: "r"(addr), "r"(parity) : "memory");
}

// ======================= FPS body (templated on cluster width) =======================
// Exchange: each warp publishes its warp-winner key (u64: valbits<<32 | ~idx)
// directly to slot [rank*WARPS + warp] in every cluster CTA, + release-arrive.
// Consumers wait on a count=SLOTS barrier, fold 64 keys, redux-reduce, and look
// up the winner's coords in a full-cloud smem copy. No __syncthreads in the loop.
template<int CTAS, int THR>
__device__ __forceinline__ void fps_body(const float* __restrict__ pos) {
    constexpr int WARPS = THR / 32;
    constexpr int PPC   = Nn / CTAS;
    constexpr int PPT   = PPC / THR;     // 8 for both instantiations
    constexpr int PKT   = PPT / 2;       // 4
    constexpr int SLOTS = CTAS * WARPS;  // 64 for both

    extern __shared__ float s_dyn[];
    float* s_x = s_dyn;
    float* s_y = s_dyn + Nn;
    float* s_z = s_dyn + 2 * Nn;
    __shared__ u64 s_keys[2][SLOTS];
    __shared__ u64 s_bar[2];

    cg::cluster_group cl = cg::this_cluster();
    const int rank = (int)cl.block_rank();
    const int b    = blockIdx.x / CTAS;
    const int t    = threadIdx.x;
    const int lane = t & 31;
    const int warp = t >> 5;
    const float* __restrict__ p = pos + (size_t)b * Nn * 3;
    const int base = rank * PPC;

    const unsigned sb    = smem_u32(&s_bar[0]);
    const unsigned keys0 = smem_u32(&s_keys[0][0]);
    const unsigned keys1 = smem_u32(&s_keys[1][0]);

    if (t == 0) { mbar_init(sb, SLOTS); mbar_init(sb + 8, SLOTS); }

    // full-cloud coords into smem (SoA)
    for (int n = t; n < Nn; n += THR) {
        s_x[n] = p[3 * n + 0];
        s_y[n] = p[3 * n + 1];
        s_z[n] = p[3 * n + 2];
    }

    // this CTA's shard in registers (packed f32x2)
    float xx[PPT], yy[PPT], zz[PPT], dm[PPT];
#pragma unroll
    for (int i = 0; i < PPT; i++) {
        int n = base + i * THR + t;
        xx[i] = p[3 * n + 0];
        yy[i] = p[3 * n + 1];
        zz[i] = p[3 * n + 2];
        dm[i] = 1e10f;
    }
    u64 pxp[PKT], pyp[PKT], pzp[PKT];
#pragma unroll
    for (int j = 0; j < PKT; j++) {
        pxp[j] = pk2(xx[2 * j], xx[2 * j + 1]);
        pyp[j] = pk2(yy[2 * j], yy[2 * j + 1]);
        pzp[j] = pk2(zz[2 * j], zz[2 * j + 1]);
    }

    // one cluster barrier: mbarrier init + smem coords visible
    cl.sync();

    float lx = s_x[0], ly = s_y[0], lz = s_z[0];
    if (rank == 0 && t == 0) {
        size_t o = (size_t)b * Ss * 3;
        g_centers[o + 0] = lx; g_centers[o + 1] = ly; g_centers[o + 2] = lz;
    }

    unsigned ph0 = 0, ph1 = 0;

    for (int s = 1; s < Ss; s++) {
        // ---- distance update + running max (packed f32x2, bit-identical per lane) ----
        u64 nx2 = pk2(-lx, -lx), ny2 = pk2(-ly, -ly), nz2 = pk2(-lz, -lz);
        float bv0 = -1.0f, bv1 = -1.0f;
#pragma unroll
        for (int j = 0; j < PKT; j++) {
            u64 dx = add2(pxp[j], nx2);
            u64 dy = add2(pyp[j], ny2);
            u64 dz = add2(pzp[j], nz2);
            u64 d  = fma2(dz, dz, fma2(dy, dy, mul2(dx, dx)));
            float d0, d1; upk2(d, d0, d1);
            float m0 = fminf(dm[2 * j], d0);
            float m1 = fminf(dm[2 * j + 1], d1);
            dm[2 * j] = m0; dm[2 * j + 1] = m1;
            bv0 = fmaxf(bv0, m0);
            bv1 = fmaxf(bv1, m1);
        }
        float bv = fmaxf(bv0, bv1);

        // smallest local slot achieving bv (slots ascend in global index)
        int bl = 0;
#pragma unroll
        for (int i = PPT - 1; i >= 0; i--) if (dm[i] == bv) bl = i;
        unsigned gi = (unsigned)(base + bl * THR + t);

        // ---- warp argmax (value desc, index asc) ----
        unsigned vb   = __float_as_uint(bv);
        unsigned wmax = __reduce_max_sync(0xffffffffu, vb);
        unsigned cand = (vb == wmax) ? gi : 0xffffffffu;
        unsigned widx = __reduce_min_sync(0xffffffffu, cand);
        u64 key = ((u64)wmax << 32) | (u64)(unsigned)(~widx);

        // ---- direct per-warp publish to all cluster CTAs ----
        const unsigned buf = (unsigned)(s & 1);
        const unsigned kb  = buf ? keys1 : keys0;
        const unsigned bar = sb + 8u * buf;
        if (lane < CTAS) {
            unsigned slot = kb + (unsigned)(rank * WARPS + warp) * 8u;
            st_rem_u64(mapa_u32(slot, lane), key);
            mbar_arrive_rel_cluster(mapa_u32(bar, lane));
        }

        // ---- wait for all SLOTS records ----
        unsigned par = buf ? ph1 : ph0;
        mbar_wait_acq_cluster(bar, par);
        if (buf) ph1 ^= 1; else ph0 ^= 1;

        // ---- 64-key reduce: fold 2/lane, then redux on (hi, lo) lexicographic ----
        u64 k1 = s_keys[buf][lane];
        u64 k2 = s_keys[buf][lane + 32];
        u64 km = (k2 > k1) ? k2 : k1;
        unsigned hi = (unsigned)(km >> 32);
        unsigned lo = (unsigned)(km & 0xffffffffu);
        unsigned hmax = __reduce_max_sync(0xffffffffu, hi);
        unsigned cl2  = (hi == hmax) ? lo : 0u;
        unsigned lmax = __reduce_max_sync(0xffffffffu, cl2);
        int idx = (int)(~lmax);

        lx = s_x[idx]; ly = s_y[idx]; lz = s_z[idx];
        if (rank == 0 && t == 0) {
            size_t o = ((size_t)b * Ss + s) * 3;
            g_centers[o + 0] = lx; g_centers[o + 1] = ly; g_centers[o + 2] = lz;
        }
    }
}

__global__ __launch_bounds__(128, 1) __cluster_dims__(16, 1, 1)
void fps16_kernel(const float* __restrict__ pos) { fps_body<16, 128>(pos); }

__global__ __launch_bounds__(256, 1) __cluster_dims__(8, 1, 1)
void fps8_kernel(const float* __restrict__ pos) { fps_body<8, 256>(pos); }

// ======================= Ball query =======================
__global__ __launch_bounds__(256) void bq_kernel(const float* __restrict__ pos) {
    int w = (blockIdx.x * blockDim.x + threadIdx.x) >> 5;   // center id 0..B*S-1
    int lane = threadIdx.x & 31;
    if (w >= Bb * Ss) return;
    int b = w / Ss;
    int s = w - b * Ss;

    float cx = g_centers[w * 3 + 0];
    float cy = g_centers[w * 3 + 1];
    float cz = g_centers[w * 3 + 2];
    const float* __restrict__ p = pos + (size_t)b * Nn * 3;

    int selfn = b * Ss + s - b * Nn;   // remove_self_loops (only hits for b=0)
    const float rr = 0.1f * 0.1f;

    int cnt = 0;
    for (int n0 = 0; n0 < Nn; n0 += 32) {
        int n = n0 + lane;
        float x = p[n * 3 + 0], y = p[n * 3 + 1], z = p[n * 3 + 2];
        float dx = x - cx, dy = y - cy, dz = z - cz;
        float d = fmaf(dz, dz, fmaf(dy, dy, dx * dx));
        bool ok = (d <= rr) && (n != selfn);
        unsigned m = __ballot_sync(0xffffffffu, ok);
        int rank = __popc(m & ((1u << lane) - 1u));
        if (ok && (cnt + rank) < Kk) g_nbr[w * Kk + cnt + rank] = n;
        cnt += __popc(m);
        if (cnt >= Kk) { cnt = Kk; break; }
    }
    if (lane == 0) g_cnt[w] = cnt < Kk ? cnt : Kk;
}

// ======================= MLP + max aggregation =======================
#define MWPB 4       // warps per block
#define NU   4       // neighbor unroll

__global__ __launch_bounds__(128) void mlp_kernel(
    const float* __restrict__ x, const float* __restrict__ pos,
    const float* __restrict__ W1, const float* __restrict__ b1,
    const float* __restrict__ W2, const float* __restrict__ b2,
    const float* __restrict__ W3, const float* __restrict__ b3,
    float* __restrict__ out)
{
    __shared__ float sW1[FD * H1D];
    __shared__ float sb1[H1D];
    __shared__ float sW2[H1D * H2D];
    __shared__ float sb2[H2D];
    __shared__ float sb3[H3D];
    __shared__ float sF [MWPB * 36 * FD];
    __shared__ float sH1[MWPB * NU * H1D];
    __shared__ float sH2[MWPB * NU * H2D];

    const int tid = threadIdx.x;
    for (int i = tid; i < FD * H1D; i += 128) sW1[i] = W1[i];
    for (int i = tid; i < H1D * H2D; i += 128) sW2[i] = W2[i];
    if (tid < H1D) { sb1[tid] = b1[tid]; sb2[tid] = b2[tid]; }
    if (tid < H3D) sb3[tid] = b3[tid];
    __syncthreads();

    const int w = tid >> 5, lane = tid & 31;
    const int cs = blockIdx.x * MWPB + w;
    const int b = cs / Ss;
    const int cnt = g_cnt[cs];
    const float cx = g_centers[cs * 3 + 0];
    const float cy = g_centers[cs * 3 + 1];
    const float cz = g_centers[cs * 3 + 2];

    float* F = sF + w * 36 * FD;

    if (lane < cnt) {
        int n = g_nbr[cs * Kk + lane];
        int src = b * Nn + n;
        const float4* xr = reinterpret_cast<const float4*>(x + (size_t)src * Fin);
        float* f = F + lane * FD;
#pragma unroll
        for (int q = 0; q < 4; q++) {
            float4 v = xr[q];
            f[4 * q + 0] = v.x; f[4 * q + 1] = v.y; f[4 * q + 2] = v.z; f[4 * q + 3] = v.w;
        }
        f[16] = pos[src * 3 + 0] - cx;
        f[17] = pos[src * 3 + 1] - cy;
        f[18] = pos[src * 3 + 2] - cz;
    }
    if (lane == 0) {
        int src = cs;  // add_self_loops: src is the FLAT dst index
        const float4* xr = reinterpret_cast<const float4*>(x + (size_t)src * Fin);
        float* f = F + cnt * FD;
#pragma unroll
        for (int q = 0; q < 4; q++) {
            float4 v = xr[q];
            f[4 * q + 0] = v.x; f[4 * q + 1] = v.y; f[4 * q + 2] = v.z; f[4 * q + 3] = v.w;
        }
        f[16] = pos[src * 3 + 0] - cx;
        f[17] = pos[src * 3 + 1] - cy;
        f[18] = pos[src * 3 + 2] - cz;
    }
    __syncwarp();

    const int nv = cnt + 1;
    float mx0 = -3.0e38f, mx1 = -3.0e38f, mx2 = -3.0e38f, mx3 = -3.0e38f;
    float* Hb1 = sH1 + w * NU * H1D;
    float* Hb2 = sH2 + w * NU * H2D;

    for (int j0 = 0; j0 < nv; j0 += NU) {
        float a0[NU], a1[NU];
#pragma unroll
        for (int u = 0; u < NU; u++) { a0[u] = sb1[lane]; a1[u] = sb1[lane + 32]; }
#pragma unroll
        for (int i = 0; i < FD; i++) {
            float w0 = sW1[i * H1D + lane];
            float w1 = sW1[i * H1D + 32 + lane];
#pragma unroll
            for (int u = 0; u < NU; u++) {
                float f = F[(j0 + u) * FD + i];
                a0[u] = fmaf(f, w0, a0[u]);
                a1[u] = fmaf(f, w1, a1[u]);
            }
        }
#pragma unroll
        for (int u = 0; u < NU; u++) {
            Hb1[u * H1D + lane]      = fmaxf(a0[u], 0.0f);
            Hb1[u * H1D + 32 + lane] = fmaxf(a1[u], 0.0f);
        }
        __syncwarp();

#pragma unroll
        for (int u = 0; u < NU; u++) { a0[u] = sb2[lane]; a1[u] = sb2[lane + 32]; }
#pragma unroll 8
        for (int i = 0; i < H1D; i++) {
            float w0 = sW2[i * H2D + lane];
            float w1 = sW2[i * H2D + 32 + lane];
#pragma unroll
            for (int u = 0; u < NU; u++) {
                float v = Hb1[u * H1D + i];
                a0[u] = fmaf(v, w0, a0[u]);
                a1[u] = fmaf(v, w1, a1[u]);
            }
        }
#pragma unroll
        for (int u = 0; u < NU; u++) {
            Hb2[u * H2D + lane]      = fmaxf(a0[u], 0.0f);
            Hb2[u * H2D + 32 + lane] = fmaxf(a1[u], 0.0f);
        }
        __syncwarp();

        float c0[NU], c1[NU], c2[NU], c3[NU];
#pragma unroll
        for (int u = 0; u < NU; u++) {
            c0[u] = sb3[lane];      c1[u] = sb3[lane + 32];
            c2[u] = sb3[lane + 64]; c3[u] = sb3[lane + 96];
        }
#pragma unroll 4
        for (int i = 0; i < H2D; i++) {
            float w0 = __ldg(W3 + i * H3D + lane);
            float w1 = __ldg(W3 + i * H3D + 32 + lane);
            float w2 = __ldg(W3 + i * H3D + 64 + lane);
            float w3 = __ldg(W3 + i * H3D + 96 + lane);
#pragma unroll
            for (int u = 0; u < NU; u++) {
                float v = Hb2[u * H2D + i];
                c0[u] = fmaf(v, w0, c0[u]);
                c1[u] = fmaf(v, w1, c1[u]);
                c2[u] = fmaf(v, w2, c2[u]);
                c3[u] = fmaf(v, w3, c3[u]);
            }
        }
#pragma unroll
        for (int u = 0; u < NU; u++) {
            if (j0 + u < nv) {
                mx0 = fmaxf(mx0, c0[u]);
                mx1 = fmaxf(mx1, c1[u]);
                mx2 = fmaxf(mx2, c2[u]);
                mx3 = fmaxf(mx3, c3[u]);
            }
        }
        __syncwarp();
    }

    size_t o = (size_t)cs * H3D;
    out[o + lane]      = mx0;
    out[o + 32 + lane] = mx1;
    out[o + 64 + lane] = mx2;
    out[o + 96 + lane] = mx3;
}

// ======================= tail: centers + batch sections =======================
__global__ void tail_kernel(float* __restrict__ out, int out_size) {
    int i = blockIdx.x * blockDim.x + threadIdx.x;
    const int NX = Bb * Ss * H3D;
    const int NC = Bb * Ss * 3;
    const int NB = Bb * Ss;
    if (out_size >= NX + NC) {
        if (i < NC) out[NX + i] = g_centers[i];
    }
    if (out_size >= NX + NC + NB) {
        if (i < NB) out[NX + NC + i] = (float)(i / Ss);
    }
}

// ======================= launch =======================
extern "C" void kernel_launch(void* const* d_in, const int* in_sizes, int n_in,
                              void* d_out, int out_size) {
    const float* x   = (const float*)d_in[0];
    const float* pos = (const float*)d_in[1];
    const float* W1  = (const float*)d_in[3];
    const float* b1  = (const float*)d_in[4];
    const float* W2  = (const float*)d_in[5];
    const float* b2  = (const float*)d_in[6];
    const float* W3  = (const float*)d_in[7];
    const float* b3  = (const float*)d_in[8];
    float* out = (float*)d_out;

    const int fps_smem = 3 * Nn * (int)sizeof(float);   // 196608 B

    cudaFuncSetAttribute(fps16_kernel, cudaFuncAttributeMaxDynamicSharedMemorySize, fps_smem);
    cudaFuncSetAttribute(fps16_kernel, cudaFuncAttributeNonPortableClusterSizeAllowed, 1);
    cudaFuncSetAttribute(fps8_kernel,  cudaFuncAttributeMaxDynamicSharedMemorySize, fps_smem);

    // probe whether a 16-CTA cluster with this smem footprint is launchable
    int nclusters = 0;
    {
        cudaLaunchConfig_t cfg = {};
        cfg.gridDim  = dim3(Bb * 16, 1, 1);
        cfg.blockDim = dim3(128, 1, 1);
        cfg.dynamicSmemBytes = fps_smem;
        cudaLaunchAttribute attrs[1];
        attrs[0].id = cudaLaunchAttributeClusterDimension;
        attrs[0].val.clusterDim = {16, 1, 1};
        cfg.attrs = attrs;
        cfg.numAttrs = 1;
        cudaError_t e = cudaOccupancyMaxActiveClusters(&nclusters, fps16_kernel, &cfg);
        if (e != cudaSuccess) { nclusters = 0; cudaGetLastError(); }
    }

    if (nclusters >= 1) {
        fps16_kernel<<<Bb * 16, 128, fps_smem>>>(pos);
    } else {
        fps8_kernel<<<Bb * 8, 256, fps_smem>>>(pos);
    }
    bq_kernel<<<(Bb * Ss * 32) / 256, 256>>>(pos);
    mlp_kernel<<<(Bb * Ss) / MWPB, 128>>>(x, pos, W1, b1, W2, b2, W3, b3, out);
    tail_kernel<<<(Bb * Ss * 3 + 255) / 256, 256>>>(out, out_size);
}